// round 14
// baseline (speedup 1.0000x reference)
#include <cuda_runtime.h>
#include <cuda_fp16.h>
#include <cstdint>

// Problem constants (fixed by the dataset)
#define NPTS 16384   // fine points
#define MPTS 4096    // coarse points
#define CF   256     // fine feature channels
#define CC   512     // coarse feature channels
#define INCH 768     // CC + CF
#define H1   512
#define H2   512
#define BN_EPS 1e-5f

// ---------------- scratch (device globals; no runtime allocation) ----------
__device__ int    g_idx[NPTS * 3];
__device__ float  g_w[NPTS * 3];
__device__ __align__(256) float  g_Zt[(size_t)MPTS * H1];     // (W1a@fc)^T fp32 [M][512]
__device__ __align__(256) __half g_y1bt[(size_t)NPTS * H1];   // (W1b@ff)^T fp16 [N][512]
__device__ __align__(256) __half g_y1t[(size_t)NPTS * H1];    // raw y1^T fp16 [N][512]
__device__ __align__(256) __half g_A1a[H1 * CC];
__device__ __align__(256) __half g_A1b[H1 * CF];
__device__ __align__(256) __half g_A2[H2 * H1];
__device__ __align__(256) __half g_y2h[(size_t)H2 * NPTS];    // raw y2 fp16
__device__ float g_sum1[H1], g_sq1[H1], g_sum2[H2], g_sq2[H2];

// ---------------- PTX helpers (all baseline, no 103a features) -------------
__device__ __forceinline__ uint32_t smem_u32(const void* p) {
    uint32_t a;
    asm("{ .reg .u64 t; cvta.to.shared.u64 t, %1; cvt.u32.u64 %0, t; }"
        : "=r"(a) : "l"(p));
    return a;
}
__device__ __forceinline__ void cp16(uint32_t dst, const void* src) {
    asm volatile("cp.async.cg.shared.global [%0], [%1], 16;"
                 :: "r"(dst), "l"(src) : "memory");
}
#define CP_COMMIT() asm volatile("cp.async.commit_group;" ::: "memory")
#define CP_WAIT2()  asm volatile("cp.async.wait_group 2;" ::: "memory")

#define LDSM_X4(r, addr) \
    asm volatile("ldmatrix.sync.aligned.m8n8.x4.shared.b16 {%0,%1,%2,%3}, [%4];" \
                 : "=r"((r)[0]), "=r"((r)[1]), "=r"((r)[2]), "=r"((r)[3]) : "r"(addr))
#define LDSM_X2(r, addr) \
    asm volatile("ldmatrix.sync.aligned.m8n8.x2.shared.b16 {%0,%1}, [%2];" \
                 : "=r"((r)[0]), "=r"((r)[1]) : "r"(addr))
#define LDSM_X2T(r, addr) \
    asm volatile("ldmatrix.sync.aligned.m8n8.x2.trans.shared.b16 {%0,%1}, [%2];" \
                 : "=r"((r)[0]), "=r"((r)[1]) : "r"(addr))

__device__ __forceinline__ void mma_f16(float c[4], const uint32_t a[4],
                                        const uint32_t b[2]) {
    asm volatile(
        "mma.sync.aligned.m16n8k16.row.col.f32.f16.f16.f32 "
        "{%0,%1,%2,%3}, {%4,%5,%6,%7}, {%8,%9}, {%0,%1,%2,%3};"
        : "+f"(c[0]), "+f"(c[1]), "+f"(c[2]), "+f"(c[3])
        : "r"(a[0]), "r"(a[1]), "r"(a[2]), "r"(a[3]), "r"(b[0]), "r"(b[1]));
}

// ---------------- prep: W1 split + W2 convert + zero BN stats ---------------
__global__ void prep_kernel(const float* __restrict__ W1, const float* __restrict__ W2,
                            __half* __restrict__ a1a, __half* __restrict__ a1b,
                            __half* __restrict__ a2,
                            float* s1, float* q1, float* s2, float* q2)
{
    int i = blockIdx.x * 256 + threadIdx.x;
    if (i < H1 * CC) {
        a1a[i] = __float2half(W1[(i >> 9) * INCH + (i & 511)]);
        a2[i]  = __float2half(W2[i]);
    }
    if (i < H1 * CF)
        a1b[i] = __float2half(W1[(i >> 8) * INCH + CC + (i & 255)]);
    if (i < H1) { s1[i] = 0.f; q1[i] = 0.f; }
    if (i < H2) { s2[i] = 0.f; q2[i] = 0.f; }
}

// ---------------- kNN: warp per 4 queries; points packed float4 -------------
__device__ __forceinline__ void top3_insert(float d, int j,
                                            float& d0, float& d1, float& d2,
                                            int& i0, int& i1, int& i2) {
    if (d < d2) {
        if (d < d1) {
            d2 = d1; i2 = i1;
            if (d < d0) { d1 = d0; i1 = i0; d0 = d; i0 = j; }
            else        { d1 = d;  i1 = j; }
        } else { d2 = d; i2 = j; }
    }
}

static constexpr int KNN_SMEM = MPTS * 16;   // float4 per point (64 KB)

__global__ __launch_bounds__(256) void knn_kernel(
    const float* __restrict__ xf, const float* __restrict__ xc,
    int* __restrict__ idx_out, float* __restrict__ w_out)
{
    extern __shared__ float4 spts[];
    for (int j = threadIdx.x; j < MPTS; j += 256) {
        float x = xc[j], y = xc[MPTS + j], z = xc[2 * MPTS + j];
        spts[j] = make_float4(x, y, z, fmaf(x, x, fmaf(y, y, z * z)));
    }
    __syncthreads();

    const int warp = threadIdx.x >> 5;
    const int lane = threadIdx.x & 31;
    const int nb = blockIdx.x * 32 + warp * 4;

    float qx[4], qy[4], qz[4], q2x[4], q2y[4], q2z[4];
    #pragma unroll
    for (int t = 0; t < 4; t++) {
        qx[t] = xf[nb + t]; qy[t] = xf[NPTS + nb + t]; qz[t] = xf[2 * NPTS + nb + t];
        q2x[t] = -2.f * qx[t]; q2y[t] = -2.f * qy[t]; q2z[t] = -2.f * qz[t];
    }

    float d[4][3];
    int   ix[4][3];
    #pragma unroll
    for (int t = 0; t < 4; t++) {
        d[t][0] = d[t][1] = d[t][2] = 3.4e38f;
        ix[t][0] = ix[t][1] = ix[t][2] = 0;
    }

    for (int j = lane; j < MPTS; j += 32) {
        float4 p = spts[j];
        #pragma unroll
        for (int t = 0; t < 4; t++) {
            float e = fmaf(q2x[t], p.x, fmaf(q2y[t], p.y, fmaf(q2z[t], p.z, p.w)));
            top3_insert(e, j, d[t][0], d[t][1], d[t][2], ix[t][0], ix[t][1], ix[t][2]);
        }
    }

    #pragma unroll
    for (int t = 0; t < 4; t++) {
        for (int off = 16; off; off >>= 1) {
            float od0 = __shfl_xor_sync(0xffffffffu, d[t][0], off);
            float od1 = __shfl_xor_sync(0xffffffffu, d[t][1], off);
            float od2 = __shfl_xor_sync(0xffffffffu, d[t][2], off);
            int   oi0 = __shfl_xor_sync(0xffffffffu, ix[t][0], off);
            int   oi1 = __shfl_xor_sync(0xffffffffu, ix[t][1], off);
            int   oi2 = __shfl_xor_sync(0xffffffffu, ix[t][2], off);
            top3_insert(od0, oi0, d[t][0], d[t][1], d[t][2], ix[t][0], ix[t][1], ix[t][2]);
            top3_insert(od1, oi1, d[t][0], d[t][1], d[t][2], ix[t][0], ix[t][1], ix[t][2]);
            top3_insert(od2, oi2, d[t][0], d[t][1], d[t][2], ix[t][0], ix[t][1], ix[t][2]);
        }
        if (lane == 0) {
            int n = nb + t;
            float D[3];
            #pragma unroll
            for (int k = 0; k < 3; k++) {
                float4 p = spts[ix[t][k]];
                float dx = qx[t] - p.x, dy = qy[t] - p.y, dz = qz[t] - p.z;
                D[k] = fmaxf(sqrtf(fmaf(dx, dx, fmaf(dy, dy, dz * dz))), 1e-8f);
            }
            float w0 = 1.f / D[0], w1 = 1.f / D[1], w2 = 1.f / D[2];
            float inv = 1.f / (w0 + w1 + w2);
            idx_out[n * 3 + 0] = ix[t][0];
            idx_out[n * 3 + 1] = ix[t][1];
            idx_out[n * 3 + 2] = ix[t][2];
            w_out[n * 3 + 0] = w0 * inv;
            w_out[n * 3 + 1] = w1 * inv;
            w_out[n * 3 + 2] = w2 * inv;
        }
    }
}

// ---------------- shared GEMM constants --------------------------------------
// CTA tile 64(M) x 128(N); 8 warps 2(M)x4(N); warp tile 32x32; acc 32/thread.
static constexpr int ROWH = 40;                   // padded halves per A/B K-row
static constexpr int A_TILE = 64 * ROWH * 2;      // 5120 B (64m x 32k)
static constexpr int BROW = 136;                  // padded halves per [k] row
static constexpr int B_TILE2 = 32 * BROW * 2;     // 8704 B (32k x 128n)
static constexpr int STG = A_TILE + B_TILE2;      // 13824 B per stage
static constexpr int GBMN_SMEM = 4 * STG;         // 55296 (fp32 epi needs 34816)
static constexpr int STAGE2 = A_TILE + 128 * ROWH * 2;  // 15360 (A + B K-major)
static constexpr int G2_SMEM = 4 * STAGE2 + 4096;       // 65536

// ---------------- gemm_bmn: A[512][K] fp16 @ B fp32 [K][Nall] (MN-major) ----
// B loaded direct from global with inline fp16 convert; ldmatrix.trans path.
// OutT [Nall][512]: fp16 (F16OUT) or fp32. 4-stage cp.async, wait_group 2.
template<int K, bool F16OUT>
__global__ __launch_bounds__(256, 3) void gemm_bmn_kernel(
    const __half* __restrict__ A, const float* __restrict__ Bg, int Nall,
    void* __restrict__ outT)
{
    extern __shared__ __half sm[];
    const uint32_t base = smem_u32(sm);
    const int tid  = threadIdx.x;
    const int lane = tid & 31;
    const int wid  = tid >> 5;
    const int wm   = wid & 1;       // 2 M-groups of 32
    const int wn   = wid >> 1;      // 4 N-groups of 32
    const int m0 = blockIdx.y * 64;
    const int n0 = blockIdx.x * 128;
    constexpr int nsl = K >> 5;

    float acc[2][4][4] = {};

    auto loadA = [&](int s, int buf) {
        const int kt = s << 5;
        const uint32_t sb = base + buf * STG;
        int r = tid >> 2, seg = tid & 3;     // 64 rows x 4 chunks = 256
        cp16(sb + (uint32_t)(r * ROWH + seg * 8) * 2,
             A + (size_t)(m0 + r) * K + kt + seg * 8);
    };
    auto ldgB = [&](int s, float4* v) {
        const int kt = s << 5;
        #pragma unroll
        for (int i = 0; i < 4; i++) {
            int id = tid + i * 256;            // 0..1023
            int kr = id >> 5, nc4 = (id & 31) * 4;
            v[i] = *(const float4*)&Bg[(size_t)(kt + kr) * Nall + n0 + nc4];
        }
    };
    auto stsB = [&](int buf, const float4* v) {
        const uint32_t off0 = buf * STG + A_TILE;
        #pragma unroll
        for (int i = 0; i < 4; i++) {
            int id = tid + i * 256;
            int kr = id >> 5, nc4 = (id & 31) * 4;
            __half o[4];
            o[0] = __float2half(v[i].x); o[1] = __float2half(v[i].y);
            o[2] = __float2half(v[i].z); o[3] = __float2half(v[i].w);
            *(uint2*)((char*)sm + off0 + (uint32_t)(kr * BROW + nc4) * 2)
                = *(const uint2*)o;
        }
    };

    auto compute = [&](int buf) {
        const uint32_t sbA = base + buf * STG;
        const uint32_t sbB = sbA + A_TILE;
        #pragma unroll
        for (int kk = 0; kk < 2; kk++) {
            const int kh = kk * 16;
            uint32_t fB[4][2];
            const int krow = kh + (lane & 15);
            #pragma unroll
            for (int ni = 0; ni < 4; ni++)
                LDSM_X2T(fB[ni], sbB +
                         (uint32_t)(krow * BROW + wn * 32 + ni * 8) * 2);
            const int arow = wm * 32 + (lane & 15);
            const int acol = kh + ((lane >> 4) << 3);
            uint32_t fA[2][4];
            #pragma unroll
            for (int mi = 0; mi < 2; mi++)
                LDSM_X4(fA[mi], sbA + (uint32_t)((arow + mi * 16) * ROWH + acol) * 2);
            #pragma unroll
            for (int mi = 0; mi < 2; mi++)
                #pragma unroll
                for (int ni = 0; ni < 4; ni++)
                    mma_f16(acc[mi][ni], fA[mi], fB[ni]);
        }
    };

    {
        float4 v0[4], v1[4], v2[4];
        ldgB(0, v0); loadA(0, 0); CP_COMMIT();
        ldgB(1, v1); loadA(1, 1); CP_COMMIT();
        ldgB(2, v2); loadA(2, 2); CP_COMMIT();
        stsB(0, v0);
        stsB(1, v1);
        stsB(2, v2);
    }
    for (int s = 0; s < nsl; s++) {
        CP_WAIT2();
        __syncthreads();
        float4 vv[4];
        int ps = s + 3;
        if (ps < nsl) { ldgB(ps, vv); loadA(ps, ps & 3); }
        CP_COMMIT();
        compute(s & 3);
        if (ps < nsl) stsB(ps & 3, vv);
    }

    const int gr = lane >> 2;
    const int gc = (lane & 3) * 2;
    __syncthreads();   // pipeline smem no longer in use

    if (F16OUT) {
        __half* y = (__half*)outT;
        __half* st = sm;   // [128 n][72] halves (18432 B)
        #pragma unroll
        for (int mi = 0; mi < 2; mi++) {
            int row = wm * 32 + mi * 16 + gr;
            #pragma unroll
            for (int ni = 0; ni < 4; ni++) {
                int col = wn * 32 + ni * 8 + gc;
                st[(uint32_t)col * 72 + row]           = __float2half(acc[mi][ni][0]);
                st[(uint32_t)(col + 1) * 72 + row]     = __float2half(acc[mi][ni][1]);
                st[(uint32_t)col * 72 + row + 8]       = __float2half(acc[mi][ni][2]);
                st[(uint32_t)(col + 1) * 72 + row + 8] = __float2half(acc[mi][ni][3]);
            }
        }
        __syncthreads();
        #pragma unroll
        for (int j = 0; j < 4; j++) {
            int idx = j * 256 + tid;          // 1024 uint4 chunks
            int nl = idx >> 3, ch = idx & 7;  // 8 chunks of 8 halves per row
            uint4 v = *(const uint4*)&st[(uint32_t)nl * 72 + ch * 8];
            *(uint4*)&y[(size_t)(n0 + nl) * 512 + m0 + ch * 8] = v;
        }
    } else {
        float* y = (float*)outT;
        float* st = (float*)sm;  // [128 n][68] floats (34816 B)
        #pragma unroll
        for (int mi = 0; mi < 2; mi++) {
            int row = wm * 32 + mi * 16 + gr;
            #pragma unroll
            for (int ni = 0; ni < 4; ni++) {
                int col = wn * 32 + ni * 8 + gc;
                st[(uint32_t)col * 68 + row]           = acc[mi][ni][0];
                st[(uint32_t)(col + 1) * 68 + row]     = acc[mi][ni][1];
                st[(uint32_t)col * 68 + row + 8]       = acc[mi][ni][2];
                st[(uint32_t)(col + 1) * 68 + row + 8] = acc[mi][ni][3];
            }
        }
        __syncthreads();
        #pragma unroll
        for (int j = 0; j < 8; j++) {
            int idx = j * 256 + tid;           // 2048 float4 chunks
            int nl = idx >> 4, ch = idx & 15;  // 16 chunks of 4 floats per row
            float4 v = *(const float4*)&st[(uint32_t)nl * 68 + ch * 4];
            *(float4*)&y[(size_t)(n0 + nl) * 512 + m0 + ch * 4] = v;
        }
    }
}

// ---------------- interp2: y1 = gather(Zt) + y1b; fp16 out + BN1 stats ------
__global__ __launch_bounds__(256) void interp2_kernel(
    const float* __restrict__ Zt, const __half* __restrict__ y1bt,
    const int* __restrict__ idx, const float* __restrict__ wgt,
    __half* __restrict__ y1t, float* __restrict__ gsum, float* __restrict__ gsq)
{
    __shared__ float bsum[8][512];
    __shared__ float bsq[8][512];
    const int w = threadIdx.x >> 5;
    const int lane = threadIdx.x & 31;
    const int nb = blockIdx.x * 64 + w * 8;

    int ii[8][3]; float ww[8][3];
    #pragma unroll
    for (int t = 0; t < 8; t++) {
        int n = nb + t;
        ii[t][0] = __ldg(&idx[n * 3 + 0]);
        ii[t][1] = __ldg(&idx[n * 3 + 1]);
        ii[t][2] = __ldg(&idx[n * 3 + 2]);
        ww[t][0] = __ldg(&wgt[n * 3 + 0]);
        ww[t][1] = __ldg(&wgt[n * 3 + 1]);
        ww[t][2] = __ldg(&wgt[n * 3 + 2]);
    }

    for (int c0 = 0; c0 < 512; c0 += 32) {
        int c = c0 + lane;
        float s = 0.f, q = 0.f;
        #pragma unroll
        for (int t = 0; t < 8; t++) {
            int n = nb + t;
            float v = fmaf(ww[t][0], __ldg(&Zt[(size_t)ii[t][0] * 512 + c]),
                     fmaf(ww[t][1], __ldg(&Zt[(size_t)ii[t][1] * 512 + c]),
                          ww[t][2] * __ldg(&Zt[(size_t)ii[t][2] * 512 + c])));
            v += __half2float(__ldg(&y1bt[(size_t)n * 512 + c]));
            y1t[(size_t)n * 512 + c] = __float2half(v);
            s += v;
            q = fmaf(v, v, q);
        }
        bsum[w][c] = s;
        bsq[w][c] = q;
    }
    __syncthreads();
    for (int c = threadIdx.x; c < 512; c += 256) {
        float s = 0.f, q = 0.f;
        #pragma unroll
        for (int r = 0; r < 8; r++) { s += bsum[r][c]; q += bsq[r][c]; }
        atomicAdd(&gsum[c], s);
        atomicAdd(&gsq[c], q);
    }
}

// ---------------- GEMM2: B = y1t, inline BN1+ReLU; y2 fp16 + stats ----------
// CTA 64(M)x128(N), 4-stage, wait_group 2 (A via cp.async, B via reg-staged LDG).
__global__ __launch_bounds__(256, 3) void gemm2_kernel(
    const __half* __restrict__ A, const __half* __restrict__ B,
    const float* __restrict__ sum1, const float* __restrict__ sq1,
    const float* __restrict__ g1, const float* __restrict__ b1,
    __half* __restrict__ Ch,
    float* __restrict__ gsum, float* __restrict__ gsq)
{
    extern __shared__ __half sm[];
    const uint32_t base = smem_u32(sm);
    float* scs = (float*)((char*)sm + 4 * STAGE2);
    float* shs = scs + H1;
    const int tid  = threadIdx.x;
    const int lane = tid & 31;
    const int wid  = tid >> 5;
    const int wm   = wid & 1;
    const int wn   = wid >> 1;
    const int m0 = blockIdx.y * 64;
    const int n0 = blockIdx.x * 128;
    constexpr int K = H1;
    constexpr int nsl = K >> 5;

    for (int j = tid; j < H1; j += 256) {
        float mean = sum1[j] * (1.f / NPTS);
        float var  = sq1[j] * (1.f / NPTS) - mean * mean;
        float s    = g1[j] * rsqrtf(var + BN_EPS);
        scs[j] = s;
        shs[j] = fmaf(-mean, s, b1[j]);
    }
    __syncthreads();

    float acc[2][4][4] = {};

    auto loadA = [&](int s, int buf) {
        const int kt = s << 5;
        const uint32_t sb = base + buf * STAGE2;
        int r = tid >> 2, seg = tid & 3;
        cp16(sb + (uint32_t)(r * ROWH + seg * 8) * 2,
             A + (size_t)(m0 + r) * K + kt + seg * 8);
    };
    auto ldgB = [&](int s, uint4* v) {
        const int kt = s << 5;
        #pragma unroll
        for (int i = 0; i < 2; i++) {
            int id = tid + i * 256;
            int r = id >> 2, seg = id & 3;
            v[i] = *(const uint4*)&B[(size_t)(n0 + r) * K + kt + seg * 8];
        }
    };
    auto stsB = [&](int s, int buf, const uint4* v) {
        const int kt = s << 5;
        const uint32_t off0 = buf * STAGE2 + A_TILE;
        #pragma unroll
        for (int i = 0; i < 2; i++) {
            int id = tid + i * 256;
            int r = id >> 2, seg = id & 3;
            const __half* hv = (const __half*)&v[i];
            __half o[8];
            #pragma unroll
            for (int e = 0; e < 8; e++) {
                int k = kt + seg * 8 + e;
                float f = __half2float(hv[e]);
                o[e] = __float2half(fmaxf(fmaf(scs[k], f, shs[k]), 0.f));
            }
            *(uint4*)((char*)sm + off0 + (uint32_t)(r * ROWH + seg * 8) * 2)
                = *(const uint4*)o;
        }
    };

    auto compute = [&](int buf) {
        const uint32_t sbA = base + buf * STAGE2;
        const uint32_t sbB = sbA + A_TILE;
        #pragma unroll
        for (int kk = 0; kk < 2; kk++) {
            const int kh = kk * 16;
            uint32_t fB[4][2];
            const int brow = wn * 32 + (lane & 7);
            const int bcol = kh + (((lane >> 3) & 1) << 3);
            #pragma unroll
            for (int ni = 0; ni < 4; ni++)
                LDSM_X2(fB[ni], sbB +
                        (uint32_t)((brow + ni * 8) * ROWH + bcol) * 2);
            const int arow = wm * 32 + (lane & 15);
            const int acol = kh + ((lane >> 4) << 3);
            uint32_t fA[2][4];
            #pragma unroll
            for (int mi = 0; mi < 2; mi++)
                LDSM_X4(fA[mi], sbA + (uint32_t)((arow + mi * 16) * ROWH + acol) * 2);
            #pragma unroll
            for (int mi = 0; mi < 2; mi++)
                #pragma unroll
                for (int ni = 0; ni < 4; ni++)
                    mma_f16(acc[mi][ni], fA[mi], fB[ni]);
        }
    };

    {
        uint4 v0[2], v1[2], v2[2];
        ldgB(0, v0); loadA(0, 0); CP_COMMIT();
        ldgB(1, v1); loadA(1, 1); CP_COMMIT();
        ldgB(2, v2); loadA(2, 2); CP_COMMIT();
        stsB(0, 0, v0);
        stsB(1, 1, v1);
        stsB(2, 2, v2);
    }
    for (int s = 0; s < nsl; s++) {
        CP_WAIT2();
        __syncthreads();
        uint4 vv[2];
        int ps = s + 3;
        if (ps < nsl) { ldgB(ps, vv); loadA(ps, ps & 3); }
        CP_COMMIT();
        compute(s & 3);
        if (ps < nsl) stsB(ps, ps & 3, vv);
    }

    const int gr = lane >> 2;
    const int gc = (lane & 3) * 2;
    #pragma unroll
    for (int mi = 0; mi < 2; mi++) {
        #pragma unroll
        for (int ni = 0; ni < 4; ni++) {
            int row = m0 + wm * 32 + mi * 16 + gr;
            int col = n0 + wn * 32 + ni * 8 + gc;
            *(__half2*)&Ch[(size_t)row * NPTS + col] =
                __floats2half2_rn(acc[mi][ni][0], acc[mi][ni][1]);
            *(__half2*)&Ch[(size_t)(row + 8) * NPTS + col] =
                __floats2half2_rn(acc[mi][ni][2], acc[mi][ni][3]);
        }
        #pragma unroll
        for (int h2 = 0; h2 < 2; h2++) {
            float s = 0.f, q = 0.f;
            #pragma unroll
            for (int ni = 0; ni < 4; ni++) {
                float v0 = acc[mi][ni][2 * h2], v1 = acc[mi][ni][2 * h2 + 1];
                s += v0 + v1;
                q += v0 * v0 + v1 * v1;
            }
            s += __shfl_xor_sync(0xffffffffu, s, 1);
            q += __shfl_xor_sync(0xffffffffu, q, 1);
            s += __shfl_xor_sync(0xffffffffu, s, 2);
            q += __shfl_xor_sync(0xffffffffu, q, 2);
            if ((lane & 3) == 0) {
                int row = m0 + wm * 32 + mi * 16 + gr + h2 * 8;
                atomicAdd(&gsum[row], s);
                atomicAdd(&gsq[row], q);
            }
        }
    }
}

// ---------------- final BN+ReLU elementwise (fp16 in, fp32 out) -------------
__global__ __launch_bounds__(256) void bn_apply_kernel(
    const __half* __restrict__ Yh,
    const float* __restrict__ sum, const float* __restrict__ sq,
    const float* __restrict__ g, const float* __restrict__ b,
    float* __restrict__ out)
{
    int i = blockIdx.x * 256 + threadIdx.x;   // 4-element groups
    int c = i >> 12;
    float mean = sum[c] * (1.f / NPTS);
    float var  = sq[c] * (1.f / NPTS) - mean * mean;
    float s    = g[c] * rsqrtf(var + BN_EPS);
    float h    = fmaf(-mean, s, b[c]);
    const __half2* Y2 = (const __half2*)Yh;
    float2 p0 = __half22float2(Y2[2 * i]);
    float2 p1 = __half22float2(Y2[2 * i + 1]);
    float4 v;
    v.x = fmaxf(fmaf(s, p0.x, h), 0.f);
    v.y = fmaxf(fmaf(s, p0.y, h), 0.f);
    v.z = fmaxf(fmaf(s, p1.x, h), 0.f);
    v.w = fmaxf(fmaf(s, p1.y, h), 0.f);
    reinterpret_cast<float4*>(out)[i] = v;
}

// ---------------- launch -----------------------------------------------------
extern "C" void kernel_launch(void* const* d_in, const int* in_sizes, int n_in,
                              void* d_out, int out_size)
{
    const float* xyz_fine     = (const float*)d_in[0];
    const float* xyz_coarse   = (const float*)d_in[1];
    const float* feats_fine   = (const float*)d_in[2];
    const float* feats_coarse = (const float*)d_in[3];
    const float* W1 = (const float*)d_in[4];
    const float* g1 = (const float*)d_in[5];
    const float* b1 = (const float*)d_in[6];
    const float* W2 = (const float*)d_in[7];
    const float* g2 = (const float*)d_in[8];
    const float* b2 = (const float*)d_in[9];
    float* out = (float*)d_out;

    void* p;
    cudaGetSymbolAddress(&p, g_idx);  int*    idxp = (int*)p;
    cudaGetSymbolAddress(&p, g_w);    float*  wp   = (float*)p;
    cudaGetSymbolAddress(&p, g_Zt);   float*  Zt   = (float*)p;
    cudaGetSymbolAddress(&p, g_y1bt); __half* y1bt = (__half*)p;
    cudaGetSymbolAddress(&p, g_y1t);  __half* y1t  = (__half*)p;
    cudaGetSymbolAddress(&p, g_A1a);  __half* a1a  = (__half*)p;
    cudaGetSymbolAddress(&p, g_A1b);  __half* a1b  = (__half*)p;
    cudaGetSymbolAddress(&p, g_A2);   __half* a2   = (__half*)p;
    cudaGetSymbolAddress(&p, g_y2h);  __half* y2h  = (__half*)p;
    cudaGetSymbolAddress(&p, g_sum1); float*  sum1 = (float*)p;
    cudaGetSymbolAddress(&p, g_sq1);  float*  sq1  = (float*)p;
    cudaGetSymbolAddress(&p, g_sum2); float*  sum2 = (float*)p;
    cudaGetSymbolAddress(&p, g_sq2);  float*  sq2  = (float*)p;

    cudaFuncSetAttribute(gemm_bmn_kernel<CC, false>,
                         cudaFuncAttributeMaxDynamicSharedMemorySize, GBMN_SMEM);
    cudaFuncSetAttribute(gemm_bmn_kernel<CF, true>,
                         cudaFuncAttributeMaxDynamicSharedMemorySize, GBMN_SMEM);
    cudaFuncSetAttribute(gemm2_kernel,
                         cudaFuncAttributeMaxDynamicSharedMemorySize, G2_SMEM);
    cudaFuncSetAttribute(knn_kernel,
                         cudaFuncAttributeMaxDynamicSharedMemorySize, KNN_SMEM);

    prep_kernel<<<(H1 * CC + 255) / 256, 256>>>(W1, W2, a1a, a1b, a2,
                                                sum1, sq1, sum2, sq2);
    knn_kernel<<<NPTS / 32, 256, KNN_SMEM>>>(xyz_fine, xyz_coarse, idxp, wp);
    // Z^T = (W1a @ fc)^T : [4096][512] fp32; B direct from feats_coarse
    gemm_bmn_kernel<CC, false><<<dim3(MPTS / 128, H1 / 64), 256, GBMN_SMEM>>>(
        a1a, feats_coarse, MPTS, Zt);
    // y1b^T = (W1b @ ff)^T : [16384][512] fp16; B direct from feats_fine
    gemm_bmn_kernel<CF, true><<<dim3(NPTS / 128, H1 / 64), 256, GBMN_SMEM>>>(
        a1b, feats_fine, NPTS, y1bt);
    interp2_kernel<<<NPTS / 64, 256>>>(Zt, y1bt, idxp, wp, y1t, sum1, sq1);
    gemm2_kernel<<<dim3(NPTS / 128, H2 / 64), 256, G2_SMEM>>>(
        a2, y1t, sum1, sq1, g1, b1, y2h, sum2, sq2);
    bn_apply_kernel<<<(H2 * NPTS / 4) / 256, 256>>>(
        y2h, sum2, sq2, g2, b2, out);
}

// round 15
// speedup vs baseline: 1.0789x; 1.0789x over previous
#include <cuda_runtime.h>
#include <cuda_fp16.h>
#include <cstdint>

// Problem constants (fixed by the dataset)
#define NPTS 16384   // fine points
#define MPTS 4096    // coarse points
#define CF   256     // fine feature channels
#define CC   512     // coarse feature channels
#define INCH 768     // CC + CF
#define H1   512
#define H2   512
#define BN_EPS 1e-5f

// ---------------- scratch (device globals; no runtime allocation) ----------
__device__ int    g_idx[NPTS * 3];
__device__ float  g_w[NPTS * 3];
__device__ __align__(256) float  g_Zt[(size_t)MPTS * H1];     // (W1a@fc)^T fp32 [M][512]
__device__ __align__(256) __half g_y1bt[(size_t)NPTS * H1];   // (W1b@ff)^T fp16 [N][512]
__device__ __align__(256) __half g_y1t[(size_t)NPTS * H1];    // raw y1^T fp16 [N][512]
__device__ __align__(256) __half g_A1a[H1 * CC];
__device__ __align__(256) __half g_A1b[H1 * CF];
__device__ __align__(256) __half g_A2[H2 * H1];
__device__ __align__(256) __half g_y2h[(size_t)H2 * NPTS];    // raw y2 fp16
__device__ float g_sum1[H1], g_sq1[H1], g_sum2[H2], g_sq2[H2];

// ---------------- PTX helpers (all baseline, no 103a features) -------------
__device__ __forceinline__ uint32_t smem_u32(const void* p) {
    uint32_t a;
    asm("{ .reg .u64 t; cvta.to.shared.u64 t, %1; cvt.u32.u64 %0, t; }"
        : "=r"(a) : "l"(p));
    return a;
}
__device__ __forceinline__ void cp16(uint32_t dst, const void* src) {
    asm volatile("cp.async.cg.shared.global [%0], [%1], 16;"
                 :: "r"(dst), "l"(src) : "memory");
}
#define CP_COMMIT() asm volatile("cp.async.commit_group;" ::: "memory")
#define CP_WAIT2()  asm volatile("cp.async.wait_group 2;" ::: "memory")

#define LDSM_X4(r, addr) \
    asm volatile("ldmatrix.sync.aligned.m8n8.x4.shared.b16 {%0,%1,%2,%3}, [%4];" \
                 : "=r"((r)[0]), "=r"((r)[1]), "=r"((r)[2]), "=r"((r)[3]) : "r"(addr))
#define LDSM_X4T(r, addr) \
    asm volatile("ldmatrix.sync.aligned.m8n8.x4.trans.shared.b16 {%0,%1,%2,%3}, [%4];" \
                 : "=r"((r)[0]), "=r"((r)[1]), "=r"((r)[2]), "=r"((r)[3]) : "r"(addr))

__device__ __forceinline__ void mma_f16(float c[4], const uint32_t a[4],
                                        const uint32_t b[2]) {
    asm volatile(
        "mma.sync.aligned.m16n8k16.row.col.f32.f16.f16.f32 "
        "{%0,%1,%2,%3}, {%4,%5,%6,%7}, {%8,%9}, {%0,%1,%2,%3};"
        : "+f"(c[0]), "+f"(c[1]), "+f"(c[2]), "+f"(c[3])
        : "r"(a[0]), "r"(a[1]), "r"(a[2]), "r"(a[3]), "r"(b[0]), "r"(b[1]));
}

// ---------------- prep: W1 split + W2 convert + zero BN stats ---------------
__global__ void prep_kernel(const float* __restrict__ W1, const float* __restrict__ W2,
                            __half* __restrict__ a1a, __half* __restrict__ a1b,
                            __half* __restrict__ a2,
                            float* s1, float* q1, float* s2, float* q2)
{
    int i = blockIdx.x * 256 + threadIdx.x;
    if (i < H1 * CC) {
        a1a[i] = __float2half(W1[(i >> 9) * INCH + (i & 511)]);
        a2[i]  = __float2half(W2[i]);
    }
    if (i < H1 * CF)
        a1b[i] = __float2half(W1[(i >> 8) * INCH + CC + (i & 255)]);
    if (i < H1) { s1[i] = 0.f; q1[i] = 0.f; }
    if (i < H2) { s2[i] = 0.f; q2[i] = 0.f; }
}

// ---------------- kNN: warp per 4 queries; points packed float4 -------------
__device__ __forceinline__ void top3_insert(float d, int j,
                                            float& d0, float& d1, float& d2,
                                            int& i0, int& i1, int& i2) {
    if (d < d2) {
        if (d < d1) {
            d2 = d1; i2 = i1;
            if (d < d0) { d1 = d0; i1 = i0; d0 = d; i0 = j; }
            else        { d1 = d;  i1 = j; }
        } else { d2 = d; i2 = j; }
    }
}

static constexpr int KNN_SMEM = MPTS * 16;   // float4 per point (64 KB)

__global__ __launch_bounds__(256) void knn_kernel(
    const float* __restrict__ xf, const float* __restrict__ xc,
    int* __restrict__ idx_out, float* __restrict__ w_out)
{
    extern __shared__ float4 spts[];
    for (int j = threadIdx.x; j < MPTS; j += 256) {
        float x = xc[j], y = xc[MPTS + j], z = xc[2 * MPTS + j];
        spts[j] = make_float4(x, y, z, fmaf(x, x, fmaf(y, y, z * z)));
    }
    __syncthreads();

    const int warp = threadIdx.x >> 5;
    const int lane = threadIdx.x & 31;
    const int nb = blockIdx.x * 32 + warp * 4;

    float qx[4], qy[4], qz[4], q2x[4], q2y[4], q2z[4];
    #pragma unroll
    for (int t = 0; t < 4; t++) {
        qx[t] = xf[nb + t]; qy[t] = xf[NPTS + nb + t]; qz[t] = xf[2 * NPTS + nb + t];
        q2x[t] = -2.f * qx[t]; q2y[t] = -2.f * qy[t]; q2z[t] = -2.f * qz[t];
    }

    float d[4][3];
    int   ix[4][3];
    #pragma unroll
    for (int t = 0; t < 4; t++) {
        d[t][0] = d[t][1] = d[t][2] = 3.4e38f;
        ix[t][0] = ix[t][1] = ix[t][2] = 0;
    }

    for (int j = lane; j < MPTS; j += 32) {
        float4 p = spts[j];
        #pragma unroll
        for (int t = 0; t < 4; t++) {
            float e = fmaf(q2x[t], p.x, fmaf(q2y[t], p.y, fmaf(q2z[t], p.z, p.w)));
            top3_insert(e, j, d[t][0], d[t][1], d[t][2], ix[t][0], ix[t][1], ix[t][2]);
        }
    }

    #pragma unroll
    for (int t = 0; t < 4; t++) {
        for (int off = 16; off; off >>= 1) {
            float od0 = __shfl_xor_sync(0xffffffffu, d[t][0], off);
            float od1 = __shfl_xor_sync(0xffffffffu, d[t][1], off);
            float od2 = __shfl_xor_sync(0xffffffffu, d[t][2], off);
            int   oi0 = __shfl_xor_sync(0xffffffffu, ix[t][0], off);
            int   oi1 = __shfl_xor_sync(0xffffffffu, ix[t][1], off);
            int   oi2 = __shfl_xor_sync(0xffffffffu, ix[t][2], off);
            top3_insert(od0, oi0, d[t][0], d[t][1], d[t][2], ix[t][0], ix[t][1], ix[t][2]);
            top3_insert(od1, oi1, d[t][0], d[t][1], d[t][2], ix[t][0], ix[t][1], ix[t][2]);
            top3_insert(od2, oi2, d[t][0], d[t][1], d[t][2], ix[t][0], ix[t][1], ix[t][2]);
        }
        if (lane == 0) {
            int n = nb + t;
            float D[3];
            #pragma unroll
            for (int k = 0; k < 3; k++) {
                float4 p = spts[ix[t][k]];
                float dx = qx[t] - p.x, dy = qy[t] - p.y, dz = qz[t] - p.z;
                D[k] = fmaxf(sqrtf(fmaf(dx, dx, fmaf(dy, dy, dz * dz))), 1e-8f);
            }
            float w0 = 1.f / D[0], w1 = 1.f / D[1], w2 = 1.f / D[2];
            float inv = 1.f / (w0 + w1 + w2);
            idx_out[n * 3 + 0] = ix[t][0];
            idx_out[n * 3 + 1] = ix[t][1];
            idx_out[n * 3 + 2] = ix[t][2];
            w_out[n * 3 + 0] = w0 * inv;
            w_out[n * 3 + 1] = w1 * inv;
            w_out[n * 3 + 2] = w2 * inv;
        }
    }
}

// ---------------- shared GEMM constants --------------------------------------
static constexpr int ROWH = 40;                   // padded halves per A row
static constexpr int A_TILE = 128 * ROWH * 2;     // 10240 B (128m x 32k)
static constexpr int BROW = 136;                  // padded halves per B [k] row
static constexpr int B_TILE2 = 32 * BROW * 2;     // 8704 B (32k x 128n)
static constexpr int STG = A_TILE + B_TILE2;      // 18944 B per stage
static constexpr int GBMN_SMEM = 4 * STG;              // 75776
static constexpr int STAGE_B = 2 * (128 * ROWH * 2);   // gemm2 stage (A+B, 20480)
static constexpr int G2_SMEM  = 4 * STAGE_B + 4096;    // 86016

// ---------------- gemm_bmn: A[512][K] fp16 @ B fp32 [K][Nall] (MN-major) ----
// B loaded direct from global with inline fp16 convert; x4.trans ldmatrix path.
// OutT [Nall][512]: fp16 (F16OUT) or fp32. 4-stage cp.async, wait_group 2.
template<int K, bool F16OUT>
__global__ __launch_bounds__(256, 2) void gemm_bmn_kernel(
    const __half* __restrict__ A, const float* __restrict__ Bg, int Nall,
    void* __restrict__ outT)
{
    extern __shared__ __half sm[];
    const uint32_t base = smem_u32(sm);
    const int tid  = threadIdx.x;
    const int lane = tid & 31;
    const int wid  = tid >> 5;
    const int wm   = wid & 1;
    const int wn   = wid >> 1;
    const int m0 = blockIdx.y * 128;
    const int n0 = blockIdx.x * 128;
    constexpr int nsl = K >> 5;

    float acc[4][4][4] = {};

    auto loadA = [&](int s, int buf) {
        const int kt = s << 5;
        const uint32_t sb = base + buf * STG;
        #pragma unroll
        for (int i = 0; i < 2; i++) {
            int id = tid + i * 256;
            int r = id >> 2, seg = id & 3;
            cp16(sb + (uint32_t)(r * ROWH + seg * 8) * 2,
                 A + (size_t)(m0 + r) * K + kt + seg * 8);
        }
    };
    auto ldgB = [&](int s, float4* v) {
        const int kt = s << 5;
        #pragma unroll
        for (int i = 0; i < 4; i++) {
            int id = tid + i * 256;            // 0..1023
            int kr = id >> 5, nc4 = (id & 31) * 4;
            v[i] = *(const float4*)&Bg[(size_t)(kt + kr) * Nall + n0 + nc4];
        }
    };
    auto stsB = [&](int buf, const float4* v) {
        const uint32_t off0 = buf * STG + A_TILE;
        #pragma unroll
        for (int i = 0; i < 4; i++) {
            int id = tid + i * 256;
            int kr = id >> 5, nc4 = (id & 31) * 4;
            __half o[4];
            o[0] = __float2half(v[i].x); o[1] = __float2half(v[i].y);
            o[2] = __float2half(v[i].z); o[3] = __float2half(v[i].w);
            *(uint2*)((char*)sm + off0 + (uint32_t)(kr * BROW + nc4) * 2)
                = *(const uint2*)o;
        }
    };

    auto compute = [&](int buf) {
        const uint32_t sbA = base + buf * STG;
        const uint32_t sbB = sbA + A_TILE;
        #pragma unroll
        for (int kk = 0; kk < 2; kk++) {
            const int kh = kk * 16;
            uint32_t fB[4][2];
            const int krow = kh + (lane & 15);
            // x4.trans: lanes 0-15 -> ni group, lanes 16-31 -> ni+1 group
            #pragma unroll
            for (int ni = 0; ni < 4; ni += 2) {
                uint32_t r[4];
                int col = wn * 32 + (ni + ((lane >> 4) & 1)) * 8;
                LDSM_X4T(r, sbB + (uint32_t)(krow * BROW + col) * 2);
                fB[ni][0] = r[0];     fB[ni][1] = r[1];
                fB[ni + 1][0] = r[2]; fB[ni + 1][1] = r[3];
            }
            const int arow = wm * 64 + (lane & 15);
            const int acol = kh + ((lane >> 4) << 3);
            uint32_t fA[4][4];
            #pragma unroll
            for (int mi = 0; mi < 4; mi++)
                LDSM_X4(fA[mi], sbA + (uint32_t)((arow + mi * 16) * ROWH + acol) * 2);
            #pragma unroll
            for (int mi = 0; mi < 4; mi++)
                #pragma unroll
                for (int ni = 0; ni < 4; ni++)
                    mma_f16(acc[mi][ni], fA[mi], fB[ni]);
        }
    };

    {
        float4 v0[4], v1[4], v2[4];
        ldgB(0, v0); loadA(0, 0); CP_COMMIT();
        ldgB(1, v1); loadA(1, 1); CP_COMMIT();
        ldgB(2, v2); loadA(2, 2); CP_COMMIT();
        stsB(0, v0);
        stsB(1, v1);
        stsB(2, v2);
    }
    for (int s = 0; s < nsl; s++) {
        CP_WAIT2();
        __syncthreads();
        float4 vv[4];
        int ps = s + 3;
        if (ps < nsl) { ldgB(ps, vv); loadA(ps, ps & 3); }
        CP_COMMIT();
        compute(s & 3);
        if (ps < nsl) stsB(ps & 3, vv);
    }

    const int gr = lane >> 2;
    const int gc = (lane & 3) * 2;
    __syncthreads();   // pipeline smem no longer in use

    if (F16OUT) {
        __half* y = (__half*)outT;
        __half* st = sm;   // [128][136] halves
        #pragma unroll
        for (int mi = 0; mi < 4; mi++) {
            int row = wm * 64 + mi * 16 + gr;
            #pragma unroll
            for (int ni = 0; ni < 4; ni++) {
                int col = wn * 32 + ni * 8 + gc;
                st[(uint32_t)col * 136 + row]           = __float2half(acc[mi][ni][0]);
                st[(uint32_t)(col + 1) * 136 + row]     = __float2half(acc[mi][ni][1]);
                st[(uint32_t)col * 136 + row + 8]       = __float2half(acc[mi][ni][2]);
                st[(uint32_t)(col + 1) * 136 + row + 8] = __float2half(acc[mi][ni][3]);
            }
        }
        __syncthreads();
        #pragma unroll
        for (int j = 0; j < 8; j++) {
            int idx = j * 256 + tid;
            int nl = idx >> 4, ch = idx & 15;
            uint4 v = *(const uint4*)&st[(uint32_t)nl * 136 + ch * 8];
            *(uint4*)&y[(size_t)(n0 + nl) * 512 + m0 + ch * 8] = v;
        }
    } else {
        float* y = (float*)outT;
        float* st = (float*)sm;  // [128][132] floats
        #pragma unroll
        for (int mi = 0; mi < 4; mi++) {
            int row = wm * 64 + mi * 16 + gr;
            #pragma unroll
            for (int ni = 0; ni < 4; ni++) {
                int col = wn * 32 + ni * 8 + gc;
                st[(uint32_t)col * 132 + row]           = acc[mi][ni][0];
                st[(uint32_t)(col + 1) * 132 + row]     = acc[mi][ni][1];
                st[(uint32_t)col * 132 + row + 8]       = acc[mi][ni][2];
                st[(uint32_t)(col + 1) * 132 + row + 8] = acc[mi][ni][3];
            }
        }
        __syncthreads();
        #pragma unroll
        for (int j = 0; j < 16; j++) {
            int idx = j * 256 + tid;
            int nl = idx >> 5, ch = idx & 31;
            float4 v = *(const float4*)&st[(uint32_t)nl * 132 + ch * 4];
            *(float4*)&y[(size_t)(n0 + nl) * 512 + m0 + ch * 4] = v;
        }
    }
}

// ---------------- interp2: y1 = gather(Zt) + y1b; fp16 out + BN1 stats ------
__global__ __launch_bounds__(256) void interp2_kernel(
    const float* __restrict__ Zt, const __half* __restrict__ y1bt,
    const int* __restrict__ idx, const float* __restrict__ wgt,
    __half* __restrict__ y1t, float* __restrict__ gsum, float* __restrict__ gsq)
{
    __shared__ float bsum[8][512];
    __shared__ float bsq[8][512];
    const int w = threadIdx.x >> 5;
    const int lane = threadIdx.x & 31;
    const int nb = blockIdx.x * 64 + w * 8;

    int ii[8][3]; float ww[8][3];
    #pragma unroll
    for (int t = 0; t < 8; t++) {
        int n = nb + t;
        ii[t][0] = __ldg(&idx[n * 3 + 0]);
        ii[t][1] = __ldg(&idx[n * 3 + 1]);
        ii[t][2] = __ldg(&idx[n * 3 + 2]);
        ww[t][0] = __ldg(&wgt[n * 3 + 0]);
        ww[t][1] = __ldg(&wgt[n * 3 + 1]);
        ww[t][2] = __ldg(&wgt[n * 3 + 2]);
    }

    for (int c0 = 0; c0 < 512; c0 += 32) {
        int c = c0 + lane;
        float s = 0.f, q = 0.f;
        #pragma unroll
        for (int t = 0; t < 8; t++) {
            int n = nb + t;
            float v = fmaf(ww[t][0], __ldg(&Zt[(size_t)ii[t][0] * 512 + c]),
                     fmaf(ww[t][1], __ldg(&Zt[(size_t)ii[t][1] * 512 + c]),
                          ww[t][2] * __ldg(&Zt[(size_t)ii[t][2] * 512 + c])));
            v += __half2float(__ldg(&y1bt[(size_t)n * 512 + c]));
            y1t[(size_t)n * 512 + c] = __float2half(v);
            s += v;
            q = fmaf(v, v, q);
        }
        bsum[w][c] = s;
        bsq[w][c] = q;
    }
    __syncthreads();
    for (int c = threadIdx.x; c < 512; c += 256) {
        float s = 0.f, q = 0.f;
        #pragma unroll
        for (int r = 0; r < 8; r++) { s += bsum[r][c]; q += bsq[r][c]; }
        atomicAdd(&gsum[c], s);
        atomicAdd(&gsq[c], q);
    }
}

// ---------------- GEMM2: B = y1t, inline BN1+ReLU; y2 fp16 + stats ----------
// 4-stage (A via cp.async, B via reg-staged LDG+transform), wait_group 2.
__global__ __launch_bounds__(256, 2) void gemm2_kernel(
    const __half* __restrict__ A, const __half* __restrict__ B,
    const float* __restrict__ sum1, const float* __restrict__ sq1,
    const float* __restrict__ g1, const float* __restrict__ b1,
    __half* __restrict__ Ch,
    float* __restrict__ gsum, float* __restrict__ gsq)
{
    extern __shared__ __half sm[];
    const uint32_t base = smem_u32(sm);
    float* scs = (float*)(sm + 4 * STAGE_B / 2);
    float* shs = scs + H1;
    const int tid  = threadIdx.x;
    const int lane = tid & 31;
    const int wid  = tid >> 5;
    const int wm   = wid & 1;
    const int wn   = wid >> 1;
    const int m0 = blockIdx.y * 128;
    const int n0 = blockIdx.x * 128;
    constexpr int K = H1;
    constexpr int nsl = K >> 5;

    for (int j = tid; j < H1; j += 256) {
        float mean = sum1[j] * (1.f / NPTS);
        float var  = sq1[j] * (1.f / NPTS) - mean * mean;
        float s    = g1[j] * rsqrtf(var + BN_EPS);
        scs[j] = s;
        shs[j] = fmaf(-mean, s, b1[j]);
    }
    __syncthreads();

    float acc[4][4][4] = {};

    auto loadA = [&](int s, int buf) {
        const int kt = s << 5;
        const uint32_t sb = base + buf * STAGE_B;
        #pragma unroll
        for (int i = 0; i < 2; i++) {
            int id = tid + i * 256;
            int r = id >> 2, seg = id & 3;
            cp16(sb + (uint32_t)(r * ROWH + seg * 8) * 2,
                 A + (size_t)(m0 + r) * K + kt + seg * 8);
        }
    };
    auto ldgB = [&](int s, uint4* v) {
        const int kt = s << 5;
        #pragma unroll
        for (int i = 0; i < 2; i++) {
            int id = tid + i * 256;
            int r = id >> 2, seg = id & 3;
            v[i] = *(const uint4*)&B[(size_t)(n0 + r) * K + kt + seg * 8];
        }
    };
    auto stsB = [&](int s, int buf, const uint4* v) {
        const int kt = s << 5;
        const uint32_t off0 = buf * STAGE_B + 128 * ROWH * 2;
        #pragma unroll
        for (int i = 0; i < 2; i++) {
            int id = tid + i * 256;
            int r = id >> 2, seg = id & 3;
            const __half* hv = (const __half*)&v[i];
            __half o[8];
            #pragma unroll
            for (int e = 0; e < 8; e++) {
                int k = kt + seg * 8 + e;
                float f = __half2float(hv[e]);
                o[e] = __float2half(fmaxf(fmaf(scs[k], f, shs[k]), 0.f));
            }
            *(uint4*)((char*)sm + off0 + (uint32_t)(r * ROWH + seg * 8) * 2)
                = *(const uint4*)o;
        }
    };

    auto compute = [&](int buf) {
        const uint32_t sb = base + buf * STAGE_B;
        const uint32_t sbB = sb + 128 * ROWH * 2;
        #pragma unroll
        for (int kk = 0; kk < 2; kk++) {
            const int kh = kk * 16;
            uint32_t fB[4][2];
            // x4 non-trans: lanes 0-7 rows of ni k-lo, 8-15 ni k-hi,
            //               16-23 ni+1 k-lo, 24-31 ni+1 k-hi
            #pragma unroll
            for (int ni = 0; ni < 4; ni += 2) {
                uint32_t r[4];
                int brow = wn * 32 + ni * 8 + ((lane >> 4) & 1) * 8 + (lane & 7);
                int bcol = kh + (((lane >> 3) & 1) << 3);
                LDSM_X4(r, sbB + (uint32_t)(brow * ROWH + bcol) * 2);
                fB[ni][0] = r[0];     fB[ni][1] = r[1];
                fB[ni + 1][0] = r[2]; fB[ni + 1][1] = r[3];
            }
            const int arow = wm * 64 + (lane & 15);
            const int acol = kh + ((lane >> 4) << 3);
            uint32_t fA[4][4];
            #pragma unroll
            for (int mi = 0; mi < 4; mi++)
                LDSM_X4(fA[mi], sb + (uint32_t)((arow + mi * 16) * ROWH + acol) * 2);
            #pragma unroll
            for (int mi = 0; mi < 4; mi++)
                #pragma unroll
                for (int ni = 0; ni < 4; ni++)
                    mma_f16(acc[mi][ni], fA[mi], fB[ni]);
        }
    };

    {
        uint4 v0[2], v1[2], v2[2];
        ldgB(0, v0); loadA(0, 0); CP_COMMIT();
        ldgB(1, v1); loadA(1, 1); CP_COMMIT();
        ldgB(2, v2); loadA(2, 2); CP_COMMIT();
        stsB(0, 0, v0);
        stsB(1, 1, v1);
        stsB(2, 2, v2);
    }
    for (int s = 0; s < nsl; s++) {
        CP_WAIT2();
        __syncthreads();
        uint4 vv[2];
        int ps = s + 3;
        if (ps < nsl) { ldgB(ps, vv); loadA(ps, ps & 3); }
        CP_COMMIT();
        compute(s & 3);
        if (ps < nsl) stsB(ps, ps & 3, vv);
    }

    const int gr = lane >> 2;
    const int gc = (lane & 3) * 2;
    #pragma unroll
    for (int mi = 0; mi < 4; mi++) {
        #pragma unroll
        for (int ni = 0; ni < 4; ni++) {
            int row = m0 + wm * 64 + mi * 16 + gr;
            int col = n0 + wn * 32 + ni * 8 + gc;
            *(__half2*)&Ch[(size_t)row * NPTS + col] =
                __floats2half2_rn(acc[mi][ni][0], acc[mi][ni][1]);
            *(__half2*)&Ch[(size_t)(row + 8) * NPTS + col] =
                __floats2half2_rn(acc[mi][ni][2], acc[mi][ni][3]);
        }
        #pragma unroll
        for (int h2 = 0; h2 < 2; h2++) {
            float s = 0.f, q = 0.f;
            #pragma unroll
            for (int ni = 0; ni < 4; ni++) {
                float v0 = acc[mi][ni][2 * h2], v1 = acc[mi][ni][2 * h2 + 1];
                s += v0 + v1;
                q += v0 * v0 + v1 * v1;
            }
            s += __shfl_xor_sync(0xffffffffu, s, 1);
            q += __shfl_xor_sync(0xffffffffu, q, 1);
            s += __shfl_xor_sync(0xffffffffu, s, 2);
            q += __shfl_xor_sync(0xffffffffu, q, 2);
            if ((lane & 3) == 0) {
                int row = m0 + wm * 64 + mi * 16 + gr + h2 * 8;
                atomicAdd(&gsum[row], s);
                atomicAdd(&gsq[row], q);
            }
        }
    }
}

// ---------------- final BN+ReLU elementwise (fp16 in, fp32 out) -------------
__global__ __launch_bounds__(256) void bn_apply_kernel(
    const __half* __restrict__ Yh,
    const float* __restrict__ sum, const float* __restrict__ sq,
    const float* __restrict__ g, const float* __restrict__ b,
    float* __restrict__ out)
{
    int i = blockIdx.x * 256 + threadIdx.x;   // 4-element groups
    int c = i >> 12;
    float mean = sum[c] * (1.f / NPTS);
    float var  = sq[c] * (1.f / NPTS) - mean * mean;
    float s    = g[c] * rsqrtf(var + BN_EPS);
    float h    = fmaf(-mean, s, b[c]);
    const __half2* Y2 = (const __half2*)Yh;
    float2 p0 = __half22float2(Y2[2 * i]);
    float2 p1 = __half22float2(Y2[2 * i + 1]);
    float4 v;
    v.x = fmaxf(fmaf(s, p0.x, h), 0.f);
    v.y = fmaxf(fmaf(s, p0.y, h), 0.f);
    v.z = fmaxf(fmaf(s, p1.x, h), 0.f);
    v.w = fmaxf(fmaf(s, p1.y, h), 0.f);
    reinterpret_cast<float4*>(out)[i] = v;
}

// ---------------- launch -----------------------------------------------------
extern "C" void kernel_launch(void* const* d_in, const int* in_sizes, int n_in,
                              void* d_out, int out_size)
{
    const float* xyz_fine     = (const float*)d_in[0];
    const float* xyz_coarse   = (const float*)d_in[1];
    const float* feats_fine   = (const float*)d_in[2];
    const float* feats_coarse = (const float*)d_in[3];
    const float* W1 = (const float*)d_in[4];
    const float* g1 = (const float*)d_in[5];
    const float* b1 = (const float*)d_in[6];
    const float* W2 = (const float*)d_in[7];
    const float* g2 = (const float*)d_in[8];
    const float* b2 = (const float*)d_in[9];
    float* out = (float*)d_out;

    void* p;
    cudaGetSymbolAddress(&p, g_idx);  int*    idxp = (int*)p;
    cudaGetSymbolAddress(&p, g_w);    float*  wp   = (float*)p;
    cudaGetSymbolAddress(&p, g_Zt);   float*  Zt   = (float*)p;
    cudaGetSymbolAddress(&p, g_y1bt); __half* y1bt = (__half*)p;
    cudaGetSymbolAddress(&p, g_y1t);  __half* y1t  = (__half*)p;
    cudaGetSymbolAddress(&p, g_A1a);  __half* a1a  = (__half*)p;
    cudaGetSymbolAddress(&p, g_A1b);  __half* a1b  = (__half*)p;
    cudaGetSymbolAddress(&p, g_A2);   __half* a2   = (__half*)p;
    cudaGetSymbolAddress(&p, g_y2h);  __half* y2h  = (__half*)p;
    cudaGetSymbolAddress(&p, g_sum1); float*  sum1 = (float*)p;
    cudaGetSymbolAddress(&p, g_sq1);  float*  sq1  = (float*)p;
    cudaGetSymbolAddress(&p, g_sum2); float*  sum2 = (float*)p;
    cudaGetSymbolAddress(&p, g_sq2);  float*  sq2  = (float*)p;

    cudaFuncSetAttribute(gemm_bmn_kernel<CC, false>,
                         cudaFuncAttributeMaxDynamicSharedMemorySize, GBMN_SMEM);
    cudaFuncSetAttribute(gemm_bmn_kernel<CF, true>,
                         cudaFuncAttributeMaxDynamicSharedMemorySize, GBMN_SMEM);
    cudaFuncSetAttribute(gemm2_kernel,
                         cudaFuncAttributeMaxDynamicSharedMemorySize, G2_SMEM);
    cudaFuncSetAttribute(knn_kernel,
                         cudaFuncAttributeMaxDynamicSharedMemorySize, KNN_SMEM);

    prep_kernel<<<(H1 * CC + 255) / 256, 256>>>(W1, W2, a1a, a1b, a2,
                                                sum1, sq1, sum2, sq2);
    knn_kernel<<<NPTS / 32, 256, KNN_SMEM>>>(xyz_fine, xyz_coarse, idxp, wp);
    // Z^T = (W1a @ fc)^T : [4096][512] fp32; B direct from feats_coarse
    gemm_bmn_kernel<CC, false><<<dim3(MPTS / 128, H1 / 128), 256, GBMN_SMEM>>>(
        a1a, feats_coarse, MPTS, Zt);
    // y1b^T = (W1b @ ff)^T : [16384][512] fp16; B direct from feats_fine
    gemm_bmn_kernel<CF, true><<<dim3(NPTS / 128, H1 / 128), 256, GBMN_SMEM>>>(
        a1b, feats_fine, NPTS, y1bt);
    interp2_kernel<<<NPTS / 64, 256>>>(Zt, y1bt, idxp, wp, y1t, sum1, sq1);
    gemm2_kernel<<<dim3(NPTS / 128, H2 / 128), 256, G2_SMEM>>>(
        a2, y1t, sum1, sq1, g1, b1, y2h, sum2, sq2);
    bn_apply_kernel<<<(H2 * NPTS / 4) / 256, 256>>>(
        y2h, sum2, sq2, g2, b2, out);
}

// round 16
// speedup vs baseline: 1.1657x; 1.0805x over previous
#include <cuda_runtime.h>
#include <cuda_fp16.h>
#include <cstdint>

// Problem constants (fixed by the dataset)
#define NPTS 16384   // fine points
#define MPTS 4096    // coarse points
#define CF   256     // fine feature channels
#define CC   512     // coarse feature channels
#define INCH 768     // CC + CF
#define H1   512
#define H2   512
#define BN_EPS 1e-5f

// ---------------- scratch (device globals; no runtime allocation) ----------
__device__ int    g_idx[NPTS * 3];
__device__ float  g_w[NPTS * 3];
__device__ __align__(256) float  g_Zt[(size_t)MPTS * H1];     // (W1a@fc)^T fp32 [M][512]
__device__ __align__(256) __half g_y1bt[(size_t)NPTS * H1];   // (W1b@ff)^T fp16 [N][512]
__device__ __align__(256) __half g_y1t[(size_t)NPTS * H1];    // raw y1^T fp16 [N][512]
__device__ __align__(256) __half g_A1a[H1 * CC];
__device__ __align__(256) __half g_A1b[H1 * CF];
__device__ __align__(256) __half g_A2[H2 * H1];
__device__ __align__(256) __half g_y2h[(size_t)H2 * NPTS];    // raw y2 fp16
__device__ float g_sum1[H1], g_sq1[H1], g_sum2[H2], g_sq2[H2];

// ---------------- PTX helpers (all baseline, no 103a features) -------------
__device__ __forceinline__ uint32_t smem_u32(const void* p) {
    uint32_t a;
    asm("{ .reg .u64 t; cvta.to.shared.u64 t, %1; cvt.u32.u64 %0, t; }"
        : "=r"(a) : "l"(p));
    return a;
}
__device__ __forceinline__ void cp16(uint32_t dst, const void* src) {
    asm volatile("cp.async.cg.shared.global [%0], [%1], 16;"
                 :: "r"(dst), "l"(src) : "memory");
}
#define CP_COMMIT() asm volatile("cp.async.commit_group;" ::: "memory")
#define CP_WAIT2()  asm volatile("cp.async.wait_group 2;" ::: "memory")

#define LDSM_X4(r, addr) \
    asm volatile("ldmatrix.sync.aligned.m8n8.x4.shared.b16 {%0,%1,%2,%3}, [%4];" \
                 : "=r"((r)[0]), "=r"((r)[1]), "=r"((r)[2]), "=r"((r)[3]) : "r"(addr))
#define LDSM_X4T(r, addr) \
    asm volatile("ldmatrix.sync.aligned.m8n8.x4.trans.shared.b16 {%0,%1,%2,%3}, [%4];" \
                 : "=r"((r)[0]), "=r"((r)[1]), "=r"((r)[2]), "=r"((r)[3]) : "r"(addr))

__device__ __forceinline__ void mma_f16(float c[4], const uint32_t a[4],
                                        const uint32_t b[2]) {
    asm volatile(
        "mma.sync.aligned.m16n8k16.row.col.f32.f16.f16.f32 "
        "{%0,%1,%2,%3}, {%4,%5,%6,%7}, {%8,%9}, {%0,%1,%2,%3};"
        : "+f"(c[0]), "+f"(c[1]), "+f"(c[2]), "+f"(c[3])
        : "r"(a[0]), "r"(a[1]), "r"(a[2]), "r"(a[3]), "r"(b[0]), "r"(b[1]));
}

// ---------------- prep: W1 split + W2 convert + zero BN stats ---------------
__global__ void prep_kernel(const float* __restrict__ W1, const float* __restrict__ W2,
                            __half* __restrict__ a1a, __half* __restrict__ a1b,
                            __half* __restrict__ a2,
                            float* s1, float* q1, float* s2, float* q2)
{
    int i = blockIdx.x * 256 + threadIdx.x;
    if (i < H1 * CC) {
        a1a[i] = __float2half(W1[(i >> 9) * INCH + (i & 511)]);
        a2[i]  = __float2half(W2[i]);
    }
    if (i < H1 * CF)
        a1b[i] = __float2half(W1[(i >> 8) * INCH + CC + (i & 255)]);
    if (i < H1) { s1[i] = 0.f; q1[i] = 0.f; }
    if (i < H2) { s2[i] = 0.f; q2[i] = 0.f; }
}

// ---------------- kNN: warp per 4 queries; points packed float4 -------------
__device__ __forceinline__ void top3_insert(float d, int j,
                                            float& d0, float& d1, float& d2,
                                            int& i0, int& i1, int& i2) {
    if (d < d2) {
        if (d < d1) {
            d2 = d1; i2 = i1;
            if (d < d0) { d1 = d0; i1 = i0; d0 = d; i0 = j; }
            else        { d1 = d;  i1 = j; }
        } else { d2 = d; i2 = j; }
    }
}

static constexpr int KNN_SMEM = MPTS * 16;   // float4 per point (64 KB)

__global__ __launch_bounds__(256) void knn_kernel(
    const float* __restrict__ xf, const float* __restrict__ xc,
    int* __restrict__ idx_out, float* __restrict__ w_out)
{
    extern __shared__ float4 spts[];
    for (int j = threadIdx.x; j < MPTS; j += 256) {
        float x = xc[j], y = xc[MPTS + j], z = xc[2 * MPTS + j];
        spts[j] = make_float4(x, y, z, fmaf(x, x, fmaf(y, y, z * z)));
    }
    __syncthreads();

    const int warp = threadIdx.x >> 5;
    const int lane = threadIdx.x & 31;
    const int nb = blockIdx.x * 32 + warp * 4;

    float qx[4], qy[4], qz[4], q2x[4], q2y[4], q2z[4];
    #pragma unroll
    for (int t = 0; t < 4; t++) {
        qx[t] = xf[nb + t]; qy[t] = xf[NPTS + nb + t]; qz[t] = xf[2 * NPTS + nb + t];
        q2x[t] = -2.f * qx[t]; q2y[t] = -2.f * qy[t]; q2z[t] = -2.f * qz[t];
    }

    float d[4][3];
    int   ix[4][3];
    #pragma unroll
    for (int t = 0; t < 4; t++) {
        d[t][0] = d[t][1] = d[t][2] = 3.4e38f;
        ix[t][0] = ix[t][1] = ix[t][2] = 0;
    }

    for (int j = lane; j < MPTS; j += 32) {
        float4 p = spts[j];
        #pragma unroll
        for (int t = 0; t < 4; t++) {
            float e = fmaf(q2x[t], p.x, fmaf(q2y[t], p.y, fmaf(q2z[t], p.z, p.w)));
            top3_insert(e, j, d[t][0], d[t][1], d[t][2], ix[t][0], ix[t][1], ix[t][2]);
        }
    }

    #pragma unroll
    for (int t = 0; t < 4; t++) {
        for (int off = 16; off; off >>= 1) {
            float od0 = __shfl_xor_sync(0xffffffffu, d[t][0], off);
            float od1 = __shfl_xor_sync(0xffffffffu, d[t][1], off);
            float od2 = __shfl_xor_sync(0xffffffffu, d[t][2], off);
            int   oi0 = __shfl_xor_sync(0xffffffffu, ix[t][0], off);
            int   oi1 = __shfl_xor_sync(0xffffffffu, ix[t][1], off);
            int   oi2 = __shfl_xor_sync(0xffffffffu, ix[t][2], off);
            top3_insert(od0, oi0, d[t][0], d[t][1], d[t][2], ix[t][0], ix[t][1], ix[t][2]);
            top3_insert(od1, oi1, d[t][0], d[t][1], d[t][2], ix[t][0], ix[t][1], ix[t][2]);
            top3_insert(od2, oi2, d[t][0], d[t][1], d[t][2], ix[t][0], ix[t][1], ix[t][2]);
        }
        if (lane == 0) {
            int n = nb + t;
            float D[3];
            #pragma unroll
            for (int k = 0; k < 3; k++) {
                float4 p = spts[ix[t][k]];
                float dx = qx[t] - p.x, dy = qy[t] - p.y, dz = qz[t] - p.z;
                D[k] = fmaxf(sqrtf(fmaf(dx, dx, fmaf(dy, dy, dz * dz))), 1e-8f);
            }
            float w0 = 1.f / D[0], w1 = 1.f / D[1], w2 = 1.f / D[2];
            float inv = 1.f / (w0 + w1 + w2);
            idx_out[n * 3 + 0] = ix[t][0];
            idx_out[n * 3 + 1] = ix[t][1];
            idx_out[n * 3 + 2] = ix[t][2];
            w_out[n * 3 + 0] = w0 * inv;
            w_out[n * 3 + 1] = w1 * inv;
            w_out[n * 3 + 2] = w2 * inv;
        }
    }
}

// ---------------- shared GEMM constants --------------------------------------
static constexpr int ROWH = 40;                   // padded halves per A row
static constexpr int A_TILE = 128 * ROWH * 2;     // 10240 B (128m x 32k)
static constexpr int BROW = 136;                  // padded halves per B [k] row
static constexpr int B_TILE2 = 32 * BROW * 2;     // 8704 B (32k x 128n)
static constexpr int STG = A_TILE + B_TILE2;      // 18944 B per stage
static constexpr int GBMN_SMEM = 4 * STG;              // 75776
static constexpr int STAGE_B = 2 * (128 * ROWH * 2);   // gemm2 stage (A+B, 20480)
static constexpr int G2_SMEM  = 4 * STAGE_B + 4096;    // 86016

// ---------------- gemm_bmn: A[512][K] fp16 @ B fp32 [K][Nall] (MN-major) ----
template<int K, bool F16OUT>
__global__ __launch_bounds__(256, 2) void gemm_bmn_kernel(
    const __half* __restrict__ A, const float* __restrict__ Bg, int Nall,
    void* __restrict__ outT)
{
    extern __shared__ __half sm[];
    const uint32_t base = smem_u32(sm);
    const int tid  = threadIdx.x;
    const int lane = tid & 31;
    const int wid  = tid >> 5;
    const int wm   = wid & 1;
    const int wn   = wid >> 1;
    const int m0 = blockIdx.y * 128;
    const int n0 = blockIdx.x * 128;
    constexpr int nsl = K >> 5;

    float acc[4][4][4] = {};

    auto loadA = [&](int s, int buf) {
        const int kt = s << 5;
        const uint32_t sb = base + buf * STG;
        #pragma unroll
        for (int i = 0; i < 2; i++) {
            int id = tid + i * 256;
            int r = id >> 2, seg = id & 3;
            cp16(sb + (uint32_t)(r * ROWH + seg * 8) * 2,
                 A + (size_t)(m0 + r) * K + kt + seg * 8);
        }
    };
    auto ldgB = [&](int s, float4* v) {
        const int kt = s << 5;
        #pragma unroll
        for (int i = 0; i < 4; i++) {
            int id = tid + i * 256;
            int kr = id >> 5, nc4 = (id & 31) * 4;
            v[i] = *(const float4*)&Bg[(size_t)(kt + kr) * Nall + n0 + nc4];
        }
    };
    auto stsB = [&](int buf, const float4* v) {
        const uint32_t off0 = buf * STG + A_TILE;
        #pragma unroll
        for (int i = 0; i < 4; i++) {
            int id = tid + i * 256;
            int kr = id >> 5, nc4 = (id & 31) * 4;
            __half o[4];
            o[0] = __float2half(v[i].x); o[1] = __float2half(v[i].y);
            o[2] = __float2half(v[i].z); o[3] = __float2half(v[i].w);
            *(uint2*)((char*)sm + off0 + (uint32_t)(kr * BROW + nc4) * 2)
                = *(const uint2*)o;
        }
    };

    auto compute = [&](int buf) {
        const uint32_t sbA = base + buf * STG;
        const uint32_t sbB = sbA + A_TILE;
        #pragma unroll
        for (int kk = 0; kk < 2; kk++) {
            const int kh = kk * 16;
            uint32_t fB[4][2];
            const int krow = kh + (lane & 15);
            #pragma unroll
            for (int ni = 0; ni < 4; ni += 2) {
                uint32_t r[4];
                int col = wn * 32 + (ni + ((lane >> 4) & 1)) * 8;
                LDSM_X4T(r, sbB + (uint32_t)(krow * BROW + col) * 2);
                fB[ni][0] = r[0];     fB[ni][1] = r[1];
                fB[ni + 1][0] = r[2]; fB[ni + 1][1] = r[3];
            }
            const int arow = wm * 64 + (lane & 15);
            const int acol = kh + ((lane >> 4) << 3);
            uint32_t fA[4][4];
            #pragma unroll
            for (int mi = 0; mi < 4; mi++)
                LDSM_X4(fA[mi], sbA + (uint32_t)((arow + mi * 16) * ROWH + acol) * 2);
            #pragma unroll
            for (int mi = 0; mi < 4; mi++)
                #pragma unroll
                for (int ni = 0; ni < 4; ni++)
                    mma_f16(acc[mi][ni], fA[mi], fB[ni]);
        }
    };

    {
        float4 v0[4], v1[4], v2[4];
        ldgB(0, v0); loadA(0, 0); CP_COMMIT();
        ldgB(1, v1); loadA(1, 1); CP_COMMIT();
        ldgB(2, v2); loadA(2, 2); CP_COMMIT();
        stsB(0, v0);
        stsB(1, v1);
        stsB(2, v2);
    }
    for (int s = 0; s < nsl; s++) {
        CP_WAIT2();
        __syncthreads();
        float4 vv[4];
        int ps = s + 3;
        if (ps < nsl) { ldgB(ps, vv); loadA(ps, ps & 3); }
        CP_COMMIT();
        compute(s & 3);
        if (ps < nsl) stsB(ps & 3, vv);
    }

    const int gr = lane >> 2;
    const int gc = (lane & 3) * 2;
    __syncthreads();

    if (F16OUT) {
        __half* y = (__half*)outT;
        __half* st = sm;   // [128][136] halves
        #pragma unroll
        for (int mi = 0; mi < 4; mi++) {
            int row = wm * 64 + mi * 16 + gr;
            #pragma unroll
            for (int ni = 0; ni < 4; ni++) {
                int col = wn * 32 + ni * 8 + gc;
                st[(uint32_t)col * 136 + row]           = __float2half(acc[mi][ni][0]);
                st[(uint32_t)(col + 1) * 136 + row]     = __float2half(acc[mi][ni][1]);
                st[(uint32_t)col * 136 + row + 8]       = __float2half(acc[mi][ni][2]);
                st[(uint32_t)(col + 1) * 136 + row + 8] = __float2half(acc[mi][ni][3]);
            }
        }
        __syncthreads();
        #pragma unroll
        for (int j = 0; j < 8; j++) {
            int idx = j * 256 + tid;
            int nl = idx >> 4, ch = idx & 15;
            uint4 v = *(const uint4*)&st[(uint32_t)nl * 136 + ch * 8];
            *(uint4*)&y[(size_t)(n0 + nl) * 512 + m0 + ch * 8] = v;
        }
    } else {
        float* y = (float*)outT;
        float* st = (float*)sm;  // [128][132] floats
        #pragma unroll
        for (int mi = 0; mi < 4; mi++) {
            int row = wm * 64 + mi * 16 + gr;
            #pragma unroll
            for (int ni = 0; ni < 4; ni++) {
                int col = wn * 32 + ni * 8 + gc;
                st[(uint32_t)col * 132 + row]           = acc[mi][ni][0];
                st[(uint32_t)(col + 1) * 132 + row]     = acc[mi][ni][1];
                st[(uint32_t)col * 132 + row + 8]       = acc[mi][ni][2];
                st[(uint32_t)(col + 1) * 132 + row + 8] = acc[mi][ni][3];
            }
        }
        __syncthreads();
        #pragma unroll
        for (int j = 0; j < 16; j++) {
            int idx = j * 256 + tid;
            int nl = idx >> 5, ch = idx & 31;
            float4 v = *(const float4*)&st[(uint32_t)nl * 132 + ch * 4];
            *(float4*)&y[(size_t)(n0 + nl) * 512 + m0 + ch * 4] = v;
        }
    }
}

// ---------------- interp2: y1 = gather(Zt) + y1b; fp16 out + BN1 stats ------
__global__ __launch_bounds__(256) void interp2_kernel(
    const float* __restrict__ Zt, const __half* __restrict__ y1bt,
    const int* __restrict__ idx, const float* __restrict__ wgt,
    __half* __restrict__ y1t, float* __restrict__ gsum, float* __restrict__ gsq)
{
    __shared__ float bsum[8][512];
    __shared__ float bsq[8][512];
    const int w = threadIdx.x >> 5;
    const int lane = threadIdx.x & 31;
    const int nb = blockIdx.x * 64 + w * 8;

    int ii[8][3]; float ww[8][3];
    #pragma unroll
    for (int t = 0; t < 8; t++) {
        int n = nb + t;
        ii[t][0] = __ldg(&idx[n * 3 + 0]);
        ii[t][1] = __ldg(&idx[n * 3 + 1]);
        ii[t][2] = __ldg(&idx[n * 3 + 2]);
        ww[t][0] = __ldg(&wgt[n * 3 + 0]);
        ww[t][1] = __ldg(&wgt[n * 3 + 1]);
        ww[t][2] = __ldg(&wgt[n * 3 + 2]);
    }

    for (int c0 = 0; c0 < 512; c0 += 32) {
        int c = c0 + lane;
        float s = 0.f, q = 0.f;
        #pragma unroll
        for (int t = 0; t < 8; t++) {
            int n = nb + t;
            float v = fmaf(ww[t][0], __ldg(&Zt[(size_t)ii[t][0] * 512 + c]),
                     fmaf(ww[t][1], __ldg(&Zt[(size_t)ii[t][1] * 512 + c]),
                          ww[t][2] * __ldg(&Zt[(size_t)ii[t][2] * 512 + c])));
            v += __half2float(__ldg(&y1bt[(size_t)n * 512 + c]));
            y1t[(size_t)n * 512 + c] = __float2half(v);
            s += v;
            q = fmaf(v, v, q);
        }
        bsum[w][c] = s;
        bsq[w][c] = q;
    }
    __syncthreads();
    for (int c = threadIdx.x; c < 512; c += 256) {
        float s = 0.f, q = 0.f;
        #pragma unroll
        for (int r = 0; r < 8; r++) { s += bsum[r][c]; q += bsq[r][c]; }
        atomicAdd(&gsum[c], s);
        atomicAdd(&gsq[c], q);
    }
}

// ---------------- GEMM2: B = y1t, inline BN1+ReLU; y2 fp16 + stats ----------
__global__ __launch_bounds__(256, 2) void gemm2_kernel(
    const __half* __restrict__ A, const __half* __restrict__ B,
    const float* __restrict__ sum1, const float* __restrict__ sq1,
    const float* __restrict__ g1, const float* __restrict__ b1,
    __half* __restrict__ Ch,
    float* __restrict__ gsum, float* __restrict__ gsq)
{
    extern __shared__ __half sm[];
    const uint32_t base = smem_u32(sm);
    float* scs = (float*)(sm + 4 * STAGE_B / 2);
    float* shs = scs + H1;
    const int tid  = threadIdx.x;
    const int lane = tid & 31;
    const int wid  = tid >> 5;
    const int wm   = wid & 1;
    const int wn   = wid >> 1;
    const int m0 = blockIdx.y * 128;
    const int n0 = blockIdx.x * 128;
    constexpr int K = H1;
    constexpr int nsl = K >> 5;

    for (int j = tid; j < H1; j += 256) {
        float mean = sum1[j] * (1.f / NPTS);
        float var  = sq1[j] * (1.f / NPTS) - mean * mean;
        float s    = g1[j] * rsqrtf(var + BN_EPS);
        scs[j] = s;
        shs[j] = fmaf(-mean, s, b1[j]);
    }
    __syncthreads();

    float acc[4][4][4] = {};

    auto loadA = [&](int s, int buf) {
        const int kt = s << 5;
        const uint32_t sb = base + buf * STAGE_B;
        #pragma unroll
        for (int i = 0; i < 2; i++) {
            int id = tid + i * 256;
            int r = id >> 2, seg = id & 3;
            cp16(sb + (uint32_t)(r * ROWH + seg * 8) * 2,
                 A + (size_t)(m0 + r) * K + kt + seg * 8);
        }
    };
    auto ldgB = [&](int s, uint4* v) {
        const int kt = s << 5;
        #pragma unroll
        for (int i = 0; i < 2; i++) {
            int id = tid + i * 256;
            int r = id >> 2, seg = id & 3;
            v[i] = *(const uint4*)&B[(size_t)(n0 + r) * K + kt + seg * 8];
        }
    };
    auto stsB = [&](int s, int buf, const uint4* v) {
        const int kt = s << 5;
        const uint32_t off0 = buf * STAGE_B + 128 * ROWH * 2;
        #pragma unroll
        for (int i = 0; i < 2; i++) {
            int id = tid + i * 256;
            int r = id >> 2, seg = id & 3;
            const __half* hv = (const __half*)&v[i];
            __half o[8];
            #pragma unroll
            for (int e = 0; e < 8; e++) {
                int k = kt + seg * 8 + e;
                float f = __half2float(hv[e]);
                o[e] = __float2half(fmaxf(fmaf(scs[k], f, shs[k]), 0.f));
            }
            *(uint4*)((char*)sm + off0 + (uint32_t)(r * ROWH + seg * 8) * 2)
                = *(const uint4*)o;
        }
    };

    auto compute = [&](int buf) {
        const uint32_t sb = base + buf * STAGE_B;
        const uint32_t sbB = sb + 128 * ROWH * 2;
        #pragma unroll
        for (int kk = 0; kk < 2; kk++) {
            const int kh = kk * 16;
            uint32_t fB[4][2];
            #pragma unroll
            for (int ni = 0; ni < 4; ni += 2) {
                uint32_t r[4];
                int brow = wn * 32 + ni * 8 + ((lane >> 4) & 1) * 8 + (lane & 7);
                int bcol = kh + (((lane >> 3) & 1) << 3);
                LDSM_X4(r, sbB + (uint32_t)(brow * ROWH + bcol) * 2);
                fB[ni][0] = r[0];     fB[ni][1] = r[1];
                fB[ni + 1][0] = r[2]; fB[ni + 1][1] = r[3];
            }
            const int arow = wm * 64 + (lane & 15);
            const int acol = kh + ((lane >> 4) << 3);
            uint32_t fA[4][4];
            #pragma unroll
            for (int mi = 0; mi < 4; mi++)
                LDSM_X4(fA[mi], sb + (uint32_t)((arow + mi * 16) * ROWH + acol) * 2);
            #pragma unroll
            for (int mi = 0; mi < 4; mi++)
                #pragma unroll
                for (int ni = 0; ni < 4; ni++)
                    mma_f16(acc[mi][ni], fA[mi], fB[ni]);
        }
    };

    {
        uint4 v0[2], v1[2], v2[2];
        ldgB(0, v0); loadA(0, 0); CP_COMMIT();
        ldgB(1, v1); loadA(1, 1); CP_COMMIT();
        ldgB(2, v2); loadA(2, 2); CP_COMMIT();
        stsB(0, 0, v0);
        stsB(1, 1, v1);
        stsB(2, 2, v2);
    }
    for (int s = 0; s < nsl; s++) {
        CP_WAIT2();
        __syncthreads();
        uint4 vv[2];
        int ps = s + 3;
        if (ps < nsl) { ldgB(ps, vv); loadA(ps, ps & 3); }
        CP_COMMIT();
        compute(s & 3);
        if (ps < nsl) stsB(ps, ps & 3, vv);
    }

    const int gr = lane >> 2;
    const int gc = (lane & 3) * 2;
    #pragma unroll
    for (int mi = 0; mi < 4; mi++) {
        #pragma unroll
        for (int ni = 0; ni < 4; ni++) {
            int row = m0 + wm * 64 + mi * 16 + gr;
            int col = n0 + wn * 32 + ni * 8 + gc;
            *(__half2*)&Ch[(size_t)row * NPTS + col] =
                __floats2half2_rn(acc[mi][ni][0], acc[mi][ni][1]);
            *(__half2*)&Ch[(size_t)(row + 8) * NPTS + col] =
                __floats2half2_rn(acc[mi][ni][2], acc[mi][ni][3]);
        }
        #pragma unroll
        for (int h2 = 0; h2 < 2; h2++) {
            float s = 0.f, q = 0.f;
            #pragma unroll
            for (int ni = 0; ni < 4; ni++) {
                float v0 = acc[mi][ni][2 * h2], v1 = acc[mi][ni][2 * h2 + 1];
                s += v0 + v1;
                q += v0 * v0 + v1 * v1;
            }
            s += __shfl_xor_sync(0xffffffffu, s, 1);
            q += __shfl_xor_sync(0xffffffffu, q, 1);
            s += __shfl_xor_sync(0xffffffffu, s, 2);
            q += __shfl_xor_sync(0xffffffffu, q, 2);
            if ((lane & 3) == 0) {
                int row = m0 + wm * 64 + mi * 16 + gr + h2 * 8;
                atomicAdd(&gsum[row], s);
                atomicAdd(&gsq[row], q);
            }
        }
    }
}

// ---------------- final BN+ReLU elementwise (fp16 in, fp32 out) -------------
__global__ __launch_bounds__(256) void bn_apply_kernel(
    const __half* __restrict__ Yh,
    const float* __restrict__ sum, const float* __restrict__ sq,
    const float* __restrict__ g, const float* __restrict__ b,
    float* __restrict__ out)
{
    int i = blockIdx.x * 256 + threadIdx.x;   // 4-element groups
    int c = i >> 12;
    float mean = sum[c] * (1.f / NPTS);
    float var  = sq[c] * (1.f / NPTS) - mean * mean;
    float s    = g[c] * rsqrtf(var + BN_EPS);
    float h    = fmaf(-mean, s, b[c]);
    const __half2* Y2 = (const __half2*)Yh;
    float2 p0 = __half22float2(Y2[2 * i]);
    float2 p1 = __half22float2(Y2[2 * i + 1]);
    float4 v;
    v.x = fmaxf(fmaf(s, p0.x, h), 0.f);
    v.y = fmaxf(fmaf(s, p0.y, h), 0.f);
    v.z = fmaxf(fmaf(s, p1.x, h), 0.f);
    v.w = fmaxf(fmaf(s, p1.y, h), 0.f);
    reinterpret_cast<float4*>(out)[i] = v;
}

// ---------------- launch -----------------------------------------------------
extern "C" void kernel_launch(void* const* d_in, const int* in_sizes, int n_in,
                              void* d_out, int out_size)
{
    const float* xyz_fine     = (const float*)d_in[0];
    const float* xyz_coarse   = (const float*)d_in[1];
    const float* feats_fine   = (const float*)d_in[2];
    const float* feats_coarse = (const float*)d_in[3];
    const float* W1 = (const float*)d_in[4];
    const float* g1 = (const float*)d_in[5];
    const float* b1 = (const float*)d_in[6];
    const float* W2 = (const float*)d_in[7];
    const float* g2 = (const float*)d_in[8];
    const float* b2 = (const float*)d_in[9];
    float* out = (float*)d_out;

    void* p;
    cudaGetSymbolAddress(&p, g_idx);  int*    idxp = (int*)p;
    cudaGetSymbolAddress(&p, g_w);    float*  wp   = (float*)p;
    cudaGetSymbolAddress(&p, g_Zt);   float*  Zt   = (float*)p;
    cudaGetSymbolAddress(&p, g_y1bt); __half* y1bt = (__half*)p;
    cudaGetSymbolAddress(&p, g_y1t);  __half* y1t  = (__half*)p;
    cudaGetSymbolAddress(&p, g_A1a);  __half* a1a  = (__half*)p;
    cudaGetSymbolAddress(&p, g_A1b);  __half* a1b  = (__half*)p;
    cudaGetSymbolAddress(&p, g_A2);   __half* a2   = (__half*)p;
    cudaGetSymbolAddress(&p, g_y2h);  __half* y2h  = (__half*)p;
    cudaGetSymbolAddress(&p, g_sum1); float*  sum1 = (float*)p;
    cudaGetSymbolAddress(&p, g_sq1);  float*  sq1  = (float*)p;
    cudaGetSymbolAddress(&p, g_sum2); float*  sum2 = (float*)p;
    cudaGetSymbolAddress(&p, g_sq2);  float*  sq2  = (float*)p;

    // lazily-created side stream + fork/join events (first call is the
    // non-capturing correctness run, so creation never happens mid-capture)
    static cudaStream_t s1 = nullptr;
    static cudaEvent_t eFork = nullptr, eJoin = nullptr;
    if (!s1) {
        cudaStreamCreateWithFlags(&s1, cudaStreamNonBlocking);
        cudaEventCreateWithFlags(&eFork, cudaEventDisableTiming);
        cudaEventCreateWithFlags(&eJoin, cudaEventDisableTiming);
        cudaFuncSetAttribute(gemm_bmn_kernel<CC, false>,
                             cudaFuncAttributeMaxDynamicSharedMemorySize, GBMN_SMEM);
        cudaFuncSetAttribute(gemm_bmn_kernel<CF, true>,
                             cudaFuncAttributeMaxDynamicSharedMemorySize, GBMN_SMEM);
        cudaFuncSetAttribute(gemm2_kernel,
                             cudaFuncAttributeMaxDynamicSharedMemorySize, G2_SMEM);
        cudaFuncSetAttribute(knn_kernel,
                             cudaFuncAttributeMaxDynamicSharedMemorySize, KNN_SMEM);
    }

    prep_kernel<<<(H1 * CC + 255) / 256, 256>>>(W1, W2, a1a, a1b, a2,
                                                sum1, sq1, sum2, sq2);

    // fork: s1 runs knn + gemmZ concurrently with gemm1b on the default stream
    cudaEventRecord(eFork, 0);
    cudaStreamWaitEvent(s1, eFork, 0);

    knn_kernel<<<NPTS / 32, 256, KNN_SMEM, s1>>>(xyz_fine, xyz_coarse, idxp, wp);
    gemm_bmn_kernel<CC, false><<<dim3(MPTS / 128, H1 / 128), 256, GBMN_SMEM, s1>>>(
        a1a, feats_coarse, MPTS, Zt);

    gemm_bmn_kernel<CF, true><<<dim3(NPTS / 128, H1 / 128), 256, GBMN_SMEM>>>(
        a1b, feats_fine, NPTS, y1bt);

    // join
    cudaEventRecord(eJoin, s1);
    cudaStreamWaitEvent(0, eJoin, 0);

    interp2_kernel<<<NPTS / 64, 256>>>(Zt, y1bt, idxp, wp, y1t, sum1, sq1);
    gemm2_kernel<<<dim3(NPTS / 128, H2 / 128), 256, G2_SMEM>>>(
        a2, y1t, sum1, sq1, g1, b1, y2h, sum2, sq2);
    bn_apply_kernel<<<(H2 * NPTS / 4) / 256, 256>>>(
        y2h, sum2, sq2, g2, b2, out);
}